// round 4
// baseline (speedup 1.0000x reference)
#include <cuda_runtime.h>

// out[b, H-1-h, w] = exp(EPS)*o[0] + sum_{d=1}^{D-1} (prod_{k<d}(1-o[k])) * o[d]
// o = clip(v, EPS, 1-EPS).
//
// Depth-split scan, NSEG=4 segments of 32 slices (R2 layout: warp = 8 rays x
// 4 segments, 2-step shuffle combine). Uniform per-element update
//   A = fma(T, o, A); T = fma(-o, T, T)
// with the d=0 weight exp(EPS) folded in post-hoc: A += (exp(EPS)-1)*o0.
// Loads batched 4 deep through an explicit register buffer (forced MLP) and
// issued with __ldcs (streaming, read-once).

#define EPSF       1e-5f
#define ONE_MEPS   (1.0f - 1e-5f)
#define EXP_EPS_M1 1.00000500002e-5f    // expf(1e-5f) - 1

static __device__ __forceinline__ float clipv(float v) {
    return fminf(fmaxf(v, EPSF), ONE_MEPS);
}

__global__ void __launch_bounds__(256)
eff_loss_kernel(const float* __restrict__ vox, float* __restrict__ out) {
    constexpr int D = 128, H = 128, W4 = 32;
    constexpr int DSTRIDE = H * W4;           // float4 stride per depth slice
    constexpr int NSEG = 4;
    constexpr int SEGD = D / NSEG;            // 32 slices per segment
    constexpr int BATCH = 4;

    int tid  = blockIdx.x * blockDim.x + threadIdx.x;  // 262144 threads
    int lane = tid & 31;
    int seg  = lane >> 3;                      // 0..3
    int ray  = (tid >> 5) * 8 + (lane & 7);    // float4-ray id, 0..65535

    int w4 = ray & (W4 - 1);
    int h  = (ray >> 5) & (H - 1);
    int b  =  ray >> 12;

    const float4* p = reinterpret_cast<const float4*>(vox)
                    + (size_t)b * D * DSTRIDE
                    + (size_t)(seg * SEGD) * DSTRIDE
                    + (size_t)h * W4 + w4;

    float ax = 0.f, ay = 0.f, az = 0.f, aw = 0.f;
    float Tx = 1.f, Ty = 1.f, Tz = 1.f, Tw = 1.f;
    float o0x = 0.f, o0y = 0.f, o0z = 0.f, o0w = 0.f;  // first clipped slice (seg 0 fix-up)

    #pragma unroll
    for (int db = 0; db < SEGD; db += BATCH) {
        float4 c[BATCH];
        #pragma unroll
        for (int j = 0; j < BATCH; ++j)
            c[j] = __ldcs(p + (size_t)(db + j) * DSTRIDE);

        #pragma unroll
        for (int j = 0; j < BATCH; ++j) {
            float cx = clipv(c[j].x), cy = clipv(c[j].y);
            float cz = clipv(c[j].z), cw = clipv(c[j].w);
            if (db == 0 && j == 0) { o0x = cx; o0y = cy; o0z = cz; o0w = cw; }
            ax = fmaf(Tx, cx, ax);   ay = fmaf(Ty, cy, ay);
            az = fmaf(Tz, cz, az);   aw = fmaf(Tw, cw, aw);
            Tx = fmaf(-cx, Tx, Tx);  Ty = fmaf(-cy, Ty, Ty);
            Tz = fmaf(-cz, Tz, Tz);  Tw = fmaf(-cw, Tw, Tw);
        }
    }

    if (seg == 0) {   // apply exp(EPS) weight to the global d=0 term
        ax = fmaf(EXP_EPS_M1, o0x, ax);  ay = fmaf(EXP_EPS_M1, o0y, ay);
        az = fmaf(EXP_EPS_M1, o0z, az);  aw = fmaf(EXP_EPS_M1, o0w, aw);
    }

    const unsigned m = 0xffffffffu;

    // combine (0,1) and (2,3): stride 8
    {
        float bax = __shfl_down_sync(m, ax, 8), bay = __shfl_down_sync(m, ay, 8);
        float baz = __shfl_down_sync(m, az, 8), baw = __shfl_down_sync(m, aw, 8);
        float btx = __shfl_down_sync(m, Tx, 8), bty = __shfl_down_sync(m, Ty, 8);
        float btz = __shfl_down_sync(m, Tz, 8), btw = __shfl_down_sync(m, Tw, 8);
        ax = fmaf(Tx, bax, ax);  ay = fmaf(Ty, bay, ay);
        az = fmaf(Tz, baz, az);  aw = fmaf(Tw, baw, aw);
        Tx *= btx;  Ty *= bty;  Tz *= btz;  Tw *= btw;
    }
    // combine (01, 23): stride 16
    {
        float bax = __shfl_down_sync(m, ax, 16), bay = __shfl_down_sync(m, ay, 16);
        float baz = __shfl_down_sync(m, az, 16), baw = __shfl_down_sync(m, aw, 16);
        ax = fmaf(Tx, bax, ax);  ay = fmaf(Ty, bay, ay);
        az = fmaf(Tz, baz, az);  aw = fmaf(Tw, baw, aw);
    }

    if (seg == 0) {
        reinterpret_cast<float4*>(out)[(size_t)b * H * W4
                                       + (size_t)(H - 1 - h) * W4 + w4]
            = make_float4(ax, ay, az, aw);
    }
}

extern "C" void kernel_launch(void* const* d_in, const int* in_sizes, int n_in,
                              void* d_out, int out_size) {
    const float* vox = (const float*)d_in[0];
    float* out = (float*)d_out;
    constexpr int TOTAL = 16 * 128 * 32 * 4;   // rays * NSEG
    eff_loss_kernel<<<TOTAL / 256, 256>>>(vox, out);
}

// round 6
// speedup vs baseline: 1.0932x; 1.0932x over previous
#include <cuda_runtime.h>

// out[b, H-1-h, w] = exp(EPS)*o[0] + sum_{d=1}^{D-1} (prod_{k<d}(1-o[k])) * o[d]
// o = clip(v, EPS, 1-EPS).
//
// Depth-split scan: D=128 into NSEG=8 segments of 16. Warp layout: 4 float4-rays
// x 8 segments (lane = seg*4 + ray). Per-segment partial pair (A_s, T_s)
// composes associatively A = A_lo + T_lo*A_hi, T = T_lo*T_hi via 3 shuffle
// steps (strides 4, 8, 16). Streaming loads (__ldcs), read-once data.

#define EPSF      1e-5f
#define ONE_MEPS  (1.0f - 1e-5f)
#define EXP_EPS   1.0000100000500002f   // expf(1e-5f)

static __device__ __forceinline__ float clipv(float v) {
    return fminf(fmaxf(v, EPSF), ONE_MEPS);
}

__global__ void __launch_bounds__(256)
eff_loss_kernel(const float* __restrict__ vox, float* __restrict__ out) {
    constexpr int D = 128, H = 128, W4 = 32;
    constexpr int DSTRIDE = H * W4;           // float4 stride per depth slice (4096)
    constexpr int NSEG = 8;
    constexpr int SEGD = D / NSEG;            // 16 slices per segment

    int tid  = blockIdx.x * blockDim.x + threadIdx.x;  // 524288 threads
    int lane = tid & 31;
    int seg  = lane >> 2;                      // 0..7
    int ray  = (tid >> 5) * 4 + (lane & 3);    // float4-ray id, 0..65535

    int w4 = ray & (W4 - 1);
    int h  = (ray >> 5) & (H - 1);
    int b  =  ray >> 12;

    const float4* p = reinterpret_cast<const float4*>(vox)
                    + (size_t)b * D * DSTRIDE
                    + (size_t)(seg * SEGD) * DSTRIDE
                    + (size_t)h * W4 + w4;

    // first slice of segment: weight exp(EPS) only for the global d=0 term
    float w0 = (seg == 0) ? EXP_EPS : 1.0f;
    float4 v0 = __ldcs(p);
    float ox = clipv(v0.x), oy = clipv(v0.y), oz = clipv(v0.z), ow = clipv(v0.w);
    float ax = w0 * ox, ay = w0 * oy, az = w0 * oz, aw = w0 * ow;
    float Tx = 1.0f, Ty = 1.0f, Tz = 1.0f, Tw = 1.0f;

    #pragma unroll 5
    for (int d = 1; d < SEGD; ++d) {
        float4 c = __ldcs(p + (size_t)d * DSTRIDE);
        float cx = clipv(c.x), cy = clipv(c.y), cz = clipv(c.z), cw = clipv(c.w);
        Tx *= (1.0f - ox);  Ty *= (1.0f - oy);
        Tz *= (1.0f - oz);  Tw *= (1.0f - ow);
        ax = fmaf(Tx, cx, ax);  ay = fmaf(Ty, cy, ay);
        az = fmaf(Tz, cz, az);  aw = fmaf(Tw, cw, aw);
        ox = cx; oy = cy; oz = cz; ow = cw;
    }
    // close the segment transmittance: include last element
    Tx *= (1.0f - ox);  Ty *= (1.0f - oy);
    Tz *= (1.0f - oz);  Tw *= (1.0f - ow);

    const unsigned m = 0xffffffffu;

    // combine adjacent segments: stride 4, then 8, then 16
    #pragma unroll
    for (int stride = 4; stride <= 8; stride <<= 1) {
        float bax = __shfl_down_sync(m, ax, stride), bay = __shfl_down_sync(m, ay, stride);
        float baz = __shfl_down_sync(m, az, stride), baw = __shfl_down_sync(m, aw, stride);
        float btx = __shfl_down_sync(m, Tx, stride), bty = __shfl_down_sync(m, Ty, stride);
        float btz = __shfl_down_sync(m, Tz, stride), btw = __shfl_down_sync(m, Tw, stride);
        ax = fmaf(Tx, bax, ax);  ay = fmaf(Ty, bay, ay);
        az = fmaf(Tz, baz, az);  aw = fmaf(Tw, baw, aw);
        Tx *= btx;  Ty *= bty;  Tz *= btz;  Tw *= btw;
    }
    // final combine: stride 16 (T no longer needed afterwards)
    {
        float bax = __shfl_down_sync(m, ax, 16), bay = __shfl_down_sync(m, ay, 16);
        float baz = __shfl_down_sync(m, az, 16), baw = __shfl_down_sync(m, aw, 16);
        ax = fmaf(Tx, bax, ax);  ay = fmaf(Ty, bay, ay);
        az = fmaf(Tz, baz, az);  aw = fmaf(Tw, baw, aw);
    }

    if (seg == 0) {
        reinterpret_cast<float4*>(out)[(size_t)b * H * W4
                                       + (size_t)(H - 1 - h) * W4 + w4]
            = make_float4(ax, ay, az, aw);
    }
}

extern "C" void kernel_launch(void* const* d_in, const int* in_sizes, int n_in,
                              void* d_out, int out_size) {
    const float* vox = (const float*)d_in[0];
    float* out = (float*)d_out;
    constexpr int TOTAL = 16 * 128 * 32 * 8;   // rays * NSEG = 524288
    eff_loss_kernel<<<TOTAL / 256, 256>>>(vox, out);
}

// round 7
// speedup vs baseline: 1.8136x; 1.6589x over previous
#include <cuda_runtime.h>

// out[b, H-1-h, w] = exp(EPS)*o[0] + sum_{d=1}^{D-1} (prod_{k<d}(1-o[k])) * o[d]
// o = clip(v, EPS, 1-EPS).
//
// Two-kernel depth-split scan, optimized for DRAM burst locality:
//   Kernel 1: D=128 split into NSEG=8 segments of 16 slices. One CTA =
//     256 threads = 256 CONSECUTIVE float4-rays of one segment, so every
//     depth step the CTA issues one 4KB fully-contiguous read (warp-level
//     512B, warps adjacent). No shuffles, no smem, no syncs. Partial pairs
//     (A_s, T_s) written to a __device__ scratch.
//   Kernel 2: folds the 8 pairs per ray (A = A_lo + T_lo*A_hi, T = T_lo*T_hi)
//     and writes the vertically-flipped output. ~9MB traffic, ~2us.

#define EPSF      1e-5f
#define ONE_MEPS  (1.0f - 1e-5f)
#define EXP_EPS   1.0000100000500002f   // expf(1e-5f)

#define D_      128
#define H_      128
#define W4_     32
#define NRAY    65536                   // B*H*W4 float4-rays
#define NSEG    8
#define SEGD    (D_ / NSEG)             // 16
#define SLICE4  (H_ * W4_)              // float4 per depth slice (4096)

__device__ float4 g_Apart[NSEG * NRAY];   // 8 MB
__device__ float4 g_Tpart[NSEG * NRAY];   // 8 MB

static __device__ __forceinline__ float clipv(float v) {
    return fminf(fmaxf(v, EPSF), ONE_MEPS);
}

__global__ void __launch_bounds__(256)
seg_scan_kernel(const float* __restrict__ vox) {
    // blockIdx: low 8 bits = ray group (256 groups of 256 rays), high bits = segment
    int group = blockIdx.x & 255;
    int seg   = blockIdx.x >> 8;
    int ray   = group * 256 + threadIdx.x;      // consecutive across the CTA

    int inSlice = ray & (SLICE4 - 1);           // (h, w4) packed, contiguous
    int b       = ray >> 14;                    // 16384 float4-rays per batch

    const float4* p = reinterpret_cast<const float4*>(vox)
                    + (size_t)b * D_ * SLICE4
                    + (size_t)(seg * SEGD) * SLICE4
                    + inSlice;

    // first slice of segment: weight exp(EPS) only for the global d=0 term
    float w0 = (seg == 0) ? EXP_EPS : 1.0f;
    float4 v0 = p[0];
    float ox = clipv(v0.x), oy = clipv(v0.y), oz = clipv(v0.z), ow = clipv(v0.w);
    float ax = w0 * ox, ay = w0 * oy, az = w0 * oz, aw = w0 * ow;
    float Tx = 1.0f, Ty = 1.0f, Tz = 1.0f, Tw = 1.0f;

    #pragma unroll 5
    for (int d = 1; d < SEGD; ++d) {
        float4 c = p[(size_t)d * SLICE4];
        float cx = clipv(c.x), cy = clipv(c.y), cz = clipv(c.z), cw = clipv(c.w);
        Tx *= (1.0f - ox);  Ty *= (1.0f - oy);
        Tz *= (1.0f - oz);  Tw *= (1.0f - ow);
        ax = fmaf(Tx, cx, ax);  ay = fmaf(Ty, cy, ay);
        az = fmaf(Tz, cz, az);  aw = fmaf(Tw, cw, aw);
        ox = cx; oy = cy; oz = cz; ow = cw;
    }
    // close the segment transmittance: include last element
    Tx *= (1.0f - ox);  Ty *= (1.0f - oy);
    Tz *= (1.0f - oz);  Tw *= (1.0f - ow);

    g_Apart[seg * NRAY + ray] = make_float4(ax, ay, az, aw);
    g_Tpart[seg * NRAY + ray] = make_float4(Tx, Ty, Tz, Tw);
}

__global__ void __launch_bounds__(256)
seg_fold_kernel(float* __restrict__ out) {
    int ray = blockIdx.x * blockDim.x + threadIdx.x;   // 65536

    float4 A = g_Apart[ray];
    float4 T = g_Tpart[ray];

    #pragma unroll
    for (int s = 1; s < NSEG; ++s) {
        float4 As = g_Apart[s * NRAY + ray];
        A.x = fmaf(T.x, As.x, A.x);  A.y = fmaf(T.y, As.y, A.y);
        A.z = fmaf(T.z, As.z, A.z);  A.w = fmaf(T.w, As.w, A.w);
        if (s < NSEG - 1) {
            float4 Ts = g_Tpart[s * NRAY + ray];
            T.x *= Ts.x;  T.y *= Ts.y;  T.z *= Ts.z;  T.w *= Ts.w;
        }
    }

    int w4 = ray & (W4_ - 1);
    int h  = (ray >> 5) & (H_ - 1);
    int b  =  ray >> 14 << 2 | ((ray >> 12) & 3);      // ray>>12 (b = ray / 4096? no)
    b = ray / (H_ * W4_);                              // safe: 4096 rays per batch

    reinterpret_cast<float4*>(out)[(size_t)b * H_ * W4_
                                   + (size_t)(H_ - 1 - h) * W4_ + w4] = A;
}

extern "C" void kernel_launch(void* const* d_in, const int* in_sizes, int n_in,
                              void* d_out, int out_size) {
    const float* vox = (const float*)d_in[0];
    float* out = (float*)d_out;
    seg_scan_kernel<<<256 * NSEG, 256>>>(vox);    // 2048 CTAs
    seg_fold_kernel<<<NRAY / 256, 256>>>(out);    // 256 CTAs
}